// round 12
// baseline (speedup 1.0000x reference)
#include <cuda_runtime.h>
#include <math.h>

#define BB 64
#define SS 1024
#define DK 128
#define DV 128
#define HALF 64
#define KST 68   // padded half-stride (floats); 68*4B keeps 16B align, shifts banks by 4

// Normalized keys (32 MB) + adjacent-key dots c[s] = kn[s-1]·kn[s] (256 KB).
__device__ float g_kn[(size_t)BB * SS * DK];
__device__ float g_c[BB * SS];

// ---------------------------------------------------------------------------
// Pre-pass (fully parallel): normalize keys, adjacent normalized dots.
// ---------------------------------------------------------------------------
__global__ void prep_kernel(const float* __restrict__ key) {
    int row = blockIdx.x * 8 + (threadIdx.x >> 5);
    int lane = threadIdx.x & 31;
    if (row >= BB * SS) return;
    int s = row & (SS - 1);

    float4 kv = reinterpret_cast<const float4*>(key)[(size_t)row * 32 + lane];
    float nn = kv.x * kv.x + kv.y * kv.y + kv.z * kv.z + kv.w * kv.w;
    float np = 0.f, dd = 0.f;
    if (s > 0) {
        float4 kp = reinterpret_cast<const float4*>(key)[(size_t)(row - 1) * 32 + lane];
        np = kp.x * kp.x + kp.y * kp.y + kp.z * kp.z + kp.w * kp.w;
        dd = kv.x * kp.x + kv.y * kp.y + kv.z * kp.z + kv.w * kp.w;
    }
    #pragma unroll
    for (int o = 16; o; o >>= 1) {
        nn += __shfl_xor_sync(0xffffffffu, nn, o);
        np += __shfl_xor_sync(0xffffffffu, np, o);
        dd += __shfl_xor_sync(0xffffffffu, dd, o);
    }
    float invn = 1.0f / (sqrtf(nn) + 1e-6f);
    float4 o4 = make_float4(kv.x * invn, kv.y * invn, kv.z * invn, kv.w * invn);
    reinterpret_cast<float4*>(g_kn)[(size_t)row * 32 + lane] = o4;
    if (lane == 0)
        g_c[row] = (s > 0) ? dd * invn * (1.0f / (sqrtf(np) + 1e-6f)) : 0.0f;
}

// ---------------------------------------------------------------------------
// Packed f32x2 helpers
// ---------------------------------------------------------------------------
__device__ __forceinline__ unsigned long long pack2(float x) {
    unsigned long long r;
    asm("mov.b64 %0, {%1, %1};" : "=l"(r) : "f"(x));
    return r;
}
__device__ __forceinline__ void fma2(unsigned long long& d,
                                     unsigned long long a, unsigned long long b) {
    asm("fma.rn.f32x2 %0, %1, %2, %0;" : "+l"(d) : "l"(a), "l"(b));
}
__device__ __forceinline__ float sum2(unsigned long long a) {
    float lo, hi;
    asm("mov.b64 {%0, %1}, %2;" : "=f"(lo), "=f"(hi) : "l"(a));
    return lo + hi;
}

// ---------------------------------------------------------------------------
// Sequential scan: one CTA per batch, 256 threads. Thread (r=t>>1, h=t&1)
// owns 64 floats of memory row r (32 f32x2 regs). Full dot recovered with
// one shfl_xor(1). One-step-deferred rank-1 update. 2 warps/SMSP.
// Main loop unrolled 6x (lcm of buffer period 3 and red parity 2) so all
// shared-buffer indices constant-fold to immediate addresses.
// ---------------------------------------------------------------------------
__global__ __launch_bounds__(256, 1) void sgm_kernel(
    const float* __restrict__ memory,
    const float* __restrict__ value,
    float* __restrict__ out)
{
    const int b = blockIdx.x;
    const int t = threadIdx.x;
    const int r = t >> 1;
    const int h = t & 1;
    const int lane = t & 31;
    const int wid = t >> 5;

    __shared__ __align__(16) float sk[3][2 * KST];
    __shared__ float red[2][8];

    const float* knb = g_kn + (size_t)b * SS * DK;
    const float* vb  = value + (size_t)b * SS * DV;
    const float* cb  = g_c + (size_t)b * SS;
    float* gates = out + (size_t)BB * DV * DK + (size_t)b * SS;

    // Load my 64-float half of memory row r as 32 packed f32x2.
    unsigned long long m2[HALF / 2];
    {
        const ulonglong2* mb = reinterpret_cast<const ulonglong2*>(
            memory + (size_t)b * DV * DK + (size_t)r * DK + h * HALF);
        #pragma unroll
        for (int j = 0; j < HALF / 4; ++j) {
            ulonglong2 x = mb[j];
            m2[2 * j] = x.x; m2[2 * j + 1] = x.y;
        }
    }

    // ---- prologue: stage k0, compute step-0 dot/reduce ----
    if (t < DK) sk[0][(t >> 6) * KST + (t & 63)] = knb[t];
    float vs = vb[r];
    float ccur = cb[1];
    __syncthreads();

    float pprev, sprev;
    {
        const ulonglong2* kc = reinterpret_cast<const ulonglong2*>(&sk[0][h * KST]);
        unsigned long long a0 = 0, a1 = 0, a2 = 0, a3 = 0;
        #pragma unroll
        for (int j = 0; j < 4; ++j) {
            ulonglong2 k0 = kc[4 * j], k1 = kc[4 * j + 1];
            ulonglong2 k2 = kc[4 * j + 2], k3 = kc[4 * j + 3];
            fma2(a0, m2[8 * j + 0], k0.x); fma2(a1, m2[8 * j + 1], k0.y);
            fma2(a2, m2[8 * j + 2], k1.x); fma2(a3, m2[8 * j + 3], k1.y);
            fma2(a0, m2[8 * j + 4], k2.x); fma2(a1, m2[8 * j + 5], k2.y);
            fma2(a2, m2[8 * j + 6], k3.x); fma2(a3, m2[8 * j + 7], k3.y);
        }
        float part = (sum2(a0) + sum2(a1)) + (sum2(a2) + sum2(a3));
        float pred = part + __shfl_xor_sync(0xffffffffu, part, 1);
        float sur = pred - vs;
        float ss2 = 0.5f * sur * sur;            // pairs duplicate -> halve
        #pragma unroll
        for (int o = 16; o; o >>= 1) ss2 += __shfl_xor_sync(0xffffffffu, ss2, o);
        if (lane == 0) red[0][wid] = ss2;
        pprev = pred; sprev = sur;
    }
    if (t < DK) sk[1][(t >> 6) * KST + (t & 63)] = knb[DK + t];
    vs = vb[DV + r];
    __syncthreads();

    int ip = 2, ic = 0, inx = 1;  // rotate at loop top -> ip=0(kn[s-1]), ic=1(kn[s])

    #pragma unroll 6
    for (int s = 1; s < SS; ++s) {
        { int tmp = ip; ip = ic; ic = inx; inx = tmp; }

        const int sn = (s + 1 < SS) ? s + 1 : s;
        float knxt = (t < DK) ? knb[(size_t)sn * DK + t] : 0.0f;
        float vnxt = vb[(size_t)sn * DV + r];
        float cnxt = cb[sn];

        // A: partial dot D = m_{s-1}[r, h-half] · kn[s]  (gate-independent)
        const ulonglong2* kc = reinterpret_cast<const ulonglong2*>(&sk[ic][h * KST]);
        unsigned long long a0 = 0, a1 = 0, a2 = 0, a3 = 0;
        #pragma unroll
        for (int j = 0; j < 4; ++j) {
            ulonglong2 k0 = kc[4 * j], k1 = kc[4 * j + 1];
            ulonglong2 k2 = kc[4 * j + 2], k3 = kc[4 * j + 3];
            fma2(a0, m2[8 * j + 0], k0.x); fma2(a1, m2[8 * j + 1], k0.y);
            fma2(a2, m2[8 * j + 2], k1.x); fma2(a3, m2[8 * j + 3], k1.y);
            fma2(a0, m2[8 * j + 4], k2.x); fma2(a1, m2[8 * j + 5], k2.y);
            fma2(a2, m2[8 * j + 6], k3.x); fma2(a3, m2[8 * j + 7], k3.y);
        }

        // B: finalize gate of step s-1
        const float* rp = red[(s - 1) & 1];
        float tot = ((rp[0] + rp[1]) + (rp[2] + rp[3]))
                  + ((rp[4] + rp[5]) + (rp[6] + rp[7]));
        float snorm = sqrtf(tot);
        float gate = 1.0f / (1.0f + __expf((0.1f - snorm) * 10.0f));
        if (t == 0) gates[s - 1] = gate;
        float u = gate * fmaf(0.1f, sprev, pprev);

        // C: deferred rank-1 update m -= u * kn[s-1]
        unsigned long long nu = pack2(-u);
        const ulonglong2* kp = reinterpret_cast<const ulonglong2*>(&sk[ip][h * KST]);
        #pragma unroll
        for (int j = 0; j < 4; ++j) {
            ulonglong2 k0 = kp[4 * j], k1 = kp[4 * j + 1];
            ulonglong2 k2 = kp[4 * j + 2], k3 = kp[4 * j + 3];
            fma2(m2[8 * j + 0], k0.x, nu); fma2(m2[8 * j + 1], k0.y, nu);
            fma2(m2[8 * j + 2], k1.x, nu); fma2(m2[8 * j + 3], k1.y, nu);
            fma2(m2[8 * j + 4], k2.x, nu); fma2(m2[8 * j + 5], k2.y, nu);
            fma2(m2[8 * j + 6], k3.x, nu); fma2(m2[8 * j + 7], k3.y, nu);
        }

        // D: assemble pred_s (with deferred correction), surprise, reduce
        float part = (sum2(a0) + sum2(a1)) + (sum2(a2) + sum2(a3));
        float pred = (part + __shfl_xor_sync(0xffffffffu, part, 1)) - u * ccur;
        float sur = pred - vs;
        float ss2 = 0.5f * sur * sur;
        #pragma unroll
        for (int o = 16; o; o >>= 1) ss2 += __shfl_xor_sync(0xffffffffu, ss2, o);
        if (lane == 0) red[s & 1][wid] = ss2;

        pprev = pred; sprev = sur; vs = vnxt; ccur = cnxt;
        if (t < DK) sk[inx][(t >> 6) * KST + (t & 63)] = knxt;
        __syncthreads();
    }

    // ---- epilogue: gate + update for step SS-1 (kn[SS-1] is in sk[ic]) ----
    {
        const float* rp = red[(SS - 1) & 1];
        float tot = ((rp[0] + rp[1]) + (rp[2] + rp[3]))
                  + ((rp[4] + rp[5]) + (rp[6] + rp[7]));
        float snorm = sqrtf(tot);
        float gate = 1.0f / (1.0f + __expf((0.1f - snorm) * 10.0f));
        if (t == 0) gates[SS - 1] = gate;
        float u = gate * fmaf(0.1f, sprev, pprev);
        unsigned long long nu = pack2(-u);
        const ulonglong2* kp = reinterpret_cast<const ulonglong2*>(&sk[ic][h * KST]);
        #pragma unroll
        for (int j = 0; j < 4; ++j) {
            ulonglong2 k0 = kp[4 * j], k1 = kp[4 * j + 1];
            ulonglong2 k2 = kp[4 * j + 2], k3 = kp[4 * j + 3];
            fma2(m2[8 * j + 0], k0.x, nu); fma2(m2[8 * j + 1], k0.y, nu);
            fma2(m2[8 * j + 2], k1.x, nu); fma2(m2[8 * j + 3], k1.y, nu);
            fma2(m2[8 * j + 4], k2.x, nu); fma2(m2[8 * j + 5], k2.y, nu);
            fma2(m2[8 * j + 6], k3.x, nu); fma2(m2[8 * j + 7], k3.y, nu);
        }
    }

    // Store final memory half.
    {
        ulonglong2* ob = reinterpret_cast<ulonglong2*>(
            out + (size_t)b * DV * DK + (size_t)r * DK + h * HALF);
        #pragma unroll
        for (int j = 0; j < HALF / 4; ++j) {
            ulonglong2 x;
            x.x = m2[2 * j]; x.y = m2[2 * j + 1];
            ob[j] = x;
        }
    }
}

extern "C" void kernel_launch(void* const* d_in, const int* in_sizes, int n_in,
                              void* d_out, int out_size) {
    const float* memory = (const float*)d_in[0];
    const float* key    = (const float*)d_in[1];
    const float* value  = (const float*)d_in[2];
    float* out = (float*)d_out;

    prep_kernel<<<(BB * SS) / 8, 256>>>(key);
    sgm_kernel<<<BB, 256>>>(memory, value, out);
}

// round 13
// speedup vs baseline: 1.1314x; 1.1314x over previous
#include <cuda_runtime.h>
#include <math.h>

#define BB 64
#define SS 1024
#define DK 128
#define DV 128
#define HALF 64
#define KST 68   // padded half-stride (floats); halves at +0 / +68

// Normalized keys (32 MB) + adjacent-key dots c[s] = kn[s-1]·kn[s] (256 KB).
__device__ float g_kn[(size_t)BB * SS * DK];
__device__ float g_c[BB * SS];

// ---------------------------------------------------------------------------
// Pre-pass (fully parallel): normalize keys, adjacent normalized dots.
// ---------------------------------------------------------------------------
__global__ void prep_kernel(const float* __restrict__ key) {
    int row = blockIdx.x * 8 + (threadIdx.x >> 5);
    int lane = threadIdx.x & 31;
    if (row >= BB * SS) return;
    int s = row & (SS - 1);

    float4 kv = reinterpret_cast<const float4*>(key)[(size_t)row * 32 + lane];
    float nn = kv.x * kv.x + kv.y * kv.y + kv.z * kv.z + kv.w * kv.w;
    float np = 0.f, dd = 0.f;
    if (s > 0) {
        float4 kp = reinterpret_cast<const float4*>(key)[(size_t)(row - 1) * 32 + lane];
        np = kp.x * kp.x + kp.y * kp.y + kp.z * kp.z + kp.w * kp.w;
        dd = kv.x * kp.x + kv.y * kp.y + kv.z * kp.z + kv.w * kp.w;
    }
    #pragma unroll
    for (int o = 16; o; o >>= 1) {
        nn += __shfl_xor_sync(0xffffffffu, nn, o);
        np += __shfl_xor_sync(0xffffffffu, np, o);
        dd += __shfl_xor_sync(0xffffffffu, dd, o);
    }
    float invn = 1.0f / (sqrtf(nn) + 1e-6f);
    float4 o4 = make_float4(kv.x * invn, kv.y * invn, kv.z * invn, kv.w * invn);
    reinterpret_cast<float4*>(g_kn)[(size_t)row * 32 + lane] = o4;
    if (lane == 0)
        g_c[row] = (s > 0) ? dd * invn * (1.0f / (sqrtf(np) + 1e-6f)) : 0.0f;
}

// ---------------------------------------------------------------------------
// Packed f32x2 helpers
// ---------------------------------------------------------------------------
__device__ __forceinline__ unsigned long long pack2(float x) {
    unsigned long long r;
    asm("mov.b64 %0, {%1, %1};" : "=l"(r) : "f"(x));
    return r;
}
__device__ __forceinline__ void fma2(unsigned long long& d,
                                     unsigned long long a, unsigned long long b) {
    asm("fma.rn.f32x2 %0, %1, %2, %0;" : "+l"(d) : "l"(a), "l"(b));
}
__device__ __forceinline__ float sum2(unsigned long long a) {
    float lo, hi;
    asm("mov.b64 {%0, %1}, %2;" : "=f"(lo), "=f"(hi) : "l"(a));
    return lo + hi;
}

// ---------------------------------------------------------------------------
// Half-step macro pieces kept EXACTLY in R4 phase order:
//   A: dot (LDS k into cache regs) -> B: gate -> C: update (cached k, no LDS)
//   -> D: pred/reduce/STS -> stage -> barrier
// ---------------------------------------------------------------------------

// One CTA per batch, 256 threads, pair layout (r=t>>1, h=t&1). Thread owns a
// 64-float half of memory row r (32 f32x2 regs). Manual 2x unroll alternates
// k-cache register sets kA/kB; update phase reads the PREVIOUS step's cached
// k registers instead of shared (16 fewer LDS.128 per step).
__global__ __launch_bounds__(256, 1) void sgm_kernel(
    const float* __restrict__ memory,
    const float* __restrict__ value,
    float* __restrict__ out)
{
    const int b = blockIdx.x;
    const int t = threadIdx.x;
    const int r = t >> 1;
    const int h = t & 1;
    const int lane = t & 31;
    const int wid = t >> 5;

    __shared__ __align__(16) float sk[2][2 * KST];
    __shared__ float red[2][8];

    const float* knb = g_kn + (size_t)b * SS * DK;
    const float* vb  = value + (size_t)b * SS * DV;
    const float* cb  = g_c + (size_t)b * SS;
    float* gates = out + (size_t)BB * DV * DK + (size_t)b * SS;

    // Load my 64-float half of memory row r as 32 packed f32x2.
    unsigned long long m2[HALF / 2];
    {
        const ulonglong2* mb = reinterpret_cast<const ulonglong2*>(
            memory + (size_t)b * DV * DK + (size_t)r * DK + h * HALF);
        #pragma unroll
        for (int j = 0; j < HALF / 4; ++j) {
            ulonglong2 x = mb[j];
            m2[2 * j] = x.x; m2[2 * j + 1] = x.y;
        }
    }

    unsigned long long kA[32], kB[32];   // cached k halves (f32x2 each)

    // ---- prologue: stage k0, compute step-0 dot/reduce (loads kB) ----
    if (t < DK) sk[0][(t >> 6) * KST + (t & 63)] = knb[t];
    float vs = vb[r];
    float ccur = cb[1];
    __syncthreads();

    float pprev, sprev;
    {
        const ulonglong2* kc = reinterpret_cast<const ulonglong2*>(&sk[0][h * KST]);
        unsigned long long a0 = 0, a1 = 0, a2 = 0, a3 = 0;
        #pragma unroll
        for (int j = 0; j < 4; ++j) {
            ulonglong2 k0 = kc[4 * j], k1 = kc[4 * j + 1];
            ulonglong2 k2 = kc[4 * j + 2], k3 = kc[4 * j + 3];
            kB[8 * j + 0] = k0.x; kB[8 * j + 1] = k0.y;
            kB[8 * j + 2] = k1.x; kB[8 * j + 3] = k1.y;
            kB[8 * j + 4] = k2.x; kB[8 * j + 5] = k2.y;
            kB[8 * j + 6] = k3.x; kB[8 * j + 7] = k3.y;
            fma2(a0, m2[8 * j + 0], k0.x); fma2(a1, m2[8 * j + 1], k0.y);
            fma2(a2, m2[8 * j + 2], k1.x); fma2(a3, m2[8 * j + 3], k1.y);
            fma2(a0, m2[8 * j + 4], k2.x); fma2(a1, m2[8 * j + 5], k2.y);
            fma2(a2, m2[8 * j + 6], k3.x); fma2(a3, m2[8 * j + 7], k3.y);
        }
        float part = (sum2(a0) + sum2(a1)) + (sum2(a2) + sum2(a3));
        float pred = part + __shfl_xor_sync(0xffffffffu, part, 1);
        float sur = pred - vs;
        float ss2 = 0.5f * sur * sur;            // pairs duplicate -> halve
        #pragma unroll
        for (int o = 16; o; o >>= 1) ss2 += __shfl_xor_sync(0xffffffffu, ss2, o);
        if (lane == 0) red[0][wid] = ss2;
        pprev = pred; sprev = sur;
    }
    if (t < DK) sk[1][(t >> 6) * KST + (t & 63)] = knb[DK + t];
    vs = vb[DV + r];
    __syncthreads();

// One half-step. BUF: shared buffer holding kn[s]; RIN: gate-partials buffer
// (s-1)&1; ROUT: s&1; KC: register set loaded by the dot; KP: previous step's
// cached k (used by the update). STG: whether to stage kn[s+1].
#define HALF_STEP(sv, BUF, RIN, ROUT, KC, KP, STG)                              \
    {                                                                           \
        const int s_ = (sv);                                                    \
        const int sn_ = (s_ + 1 < SS) ? s_ + 1 : s_;                            \
        float knxt = (t < DK) ? knb[(size_t)sn_ * DK + t] : 0.0f;               \
        float vnxt = vb[(size_t)sn_ * DV + r];                                  \
        float cnxt = cb[sn_];                                                   \
        /* A: dot with kn[s], caching k into KC */                              \
        const ulonglong2* kc = reinterpret_cast<const ulonglong2*>(&sk[BUF][h * KST]); \
        unsigned long long a0 = 0, a1 = 0, a2 = 0, a3 = 0;                      \
        _Pragma("unroll")                                                       \
        for (int j = 0; j < 4; ++j) {                                           \
            ulonglong2 k0 = kc[4 * j], k1 = kc[4 * j + 1];                      \
            ulonglong2 k2 = kc[4 * j + 2], k3 = kc[4 * j + 3];                  \
            KC[8 * j + 0] = k0.x; KC[8 * j + 1] = k0.y;                         \
            KC[8 * j + 2] = k1.x; KC[8 * j + 3] = k1.y;                         \
            KC[8 * j + 4] = k2.x; KC[8 * j + 5] = k2.y;                         \
            KC[8 * j + 6] = k3.x; KC[8 * j + 7] = k3.y;                         \
            fma2(a0, m2[8 * j + 0], k0.x); fma2(a1, m2[8 * j + 1], k0.y);       \
            fma2(a2, m2[8 * j + 2], k1.x); fma2(a3, m2[8 * j + 3], k1.y);       \
            fma2(a0, m2[8 * j + 4], k2.x); fma2(a1, m2[8 * j + 5], k2.y);       \
            fma2(a2, m2[8 * j + 6], k3.x); fma2(a3, m2[8 * j + 7], k3.y);       \
        }                                                                       \
        /* B: finalize gate of step s-1 */                                      \
        const float* rp = red[RIN];                                             \
        float tot = ((rp[0] + rp[1]) + (rp[2] + rp[3]))                         \
                  + ((rp[4] + rp[5]) + (rp[6] + rp[7]));                        \
        float snorm = sqrtf(tot);                                               \
        float gate = 1.0f / (1.0f + __expf((0.1f - snorm) * 10.0f));            \
        if (t == 0) gates[s_ - 1] = gate;                                       \
        float u = gate * fmaf(0.1f, sprev, pprev);                              \
        /* C: deferred rank-1 update m -= u * kn[s-1] from cached KP */         \
        unsigned long long nu = pack2(-u);                                      \
        _Pragma("unroll")                                                       \
        for (int j = 0; j < 8; ++j) {                                           \
            fma2(m2[4 * j + 0], KP[4 * j + 0], nu);                             \
            fma2(m2[4 * j + 1], KP[4 * j + 1], nu);                             \
            fma2(m2[4 * j + 2], KP[4 * j + 2], nu);                             \
            fma2(m2[4 * j + 3], KP[4 * j + 3], nu);                             \
        }                                                                       \
        /* D: assemble pred_s, surprise, reduce, STS */                         \
        float part = (sum2(a0) + sum2(a1)) + (sum2(a2) + sum2(a3));             \
        float pred = (part + __shfl_xor_sync(0xffffffffu, part, 1)) - u * ccur; \
        float sur = pred - vs;                                                  \
        float ss2 = 0.5f * sur * sur;                                           \
        _Pragma("unroll")                                                       \
        for (int o = 16; o; o >>= 1) ss2 += __shfl_xor_sync(0xffffffffu, ss2, o); \
        if (lane == 0) red[ROUT][wid] = ss2;                                    \
        pprev = pred; sprev = sur; vs = vnxt; ccur = cnxt;                      \
        if (STG) { if (t < DK) sk[BUF ^ 1][(t >> 6) * KST + (t & 63)] = knxt; } \
        __syncthreads();                                                        \
    }

    // ---- main loop: 511 double steps, handling s = 1..1022 ----
    for (int s = 1; s < SS - 2; s += 2) {
        HALF_STEP(s,     1, 0, 1, kA, kB, 1)   // odd step: dot kn[s] in sk[1]
        HALF_STEP(s + 1, 0, 1, 0, kB, kA, 1)   // even step: dot kn[s+1] in sk[0]
    }
    // ---- tail: step SS-1 = 1023 (odd), no staging needed ----
    HALF_STEP(SS - 1, 1, 0, 1, kA, kB, 0)

#undef HALF_STEP

    // ---- epilogue: gate + update for step SS-1 (kn[SS-1] cached in kA) ----
    {
        const float* rp = red[1];
        float tot = ((rp[0] + rp[1]) + (rp[2] + rp[3]))
                  + ((rp[4] + rp[5]) + (rp[6] + rp[7]));
        float snorm = sqrtf(tot);
        float gate = 1.0f / (1.0f + __expf((0.1f - snorm) * 10.0f));
        if (t == 0) gates[SS - 1] = gate;
        float u = gate * fmaf(0.1f, sprev, pprev);
        unsigned long long nu = pack2(-u);
        #pragma unroll
        for (int j = 0; j < 8; ++j) {
            fma2(m2[4 * j + 0], kA[4 * j + 0], nu);
            fma2(m2[4 * j + 1], kA[4 * j + 1], nu);
            fma2(m2[4 * j + 2], kA[4 * j + 2], nu);
            fma2(m2[4 * j + 3], kA[4 * j + 3], nu);
        }
    }

    // Store final memory half.
    {
        ulonglong2* ob = reinterpret_cast<ulonglong2*>(
            out + (size_t)b * DV * DK + (size_t)r * DK + h * HALF);
        #pragma unroll
        for (int j = 0; j < HALF / 4; ++j) {
            ulonglong2 x;
            x.x = m2[2 * j]; x.y = m2[2 * j + 1];
            ob[j] = x;
        }
    }
}

extern "C" void kernel_launch(void* const* d_in, const int* in_sizes, int n_in,
                              void* d_out, int out_size) {
    const float* memory = (const float*)d_in[0];
    const float* key    = (const float*)d_in[1];
    const float* value  = (const float*)d_in[2];
    float* out = (float*)d_out;

    prep_kernel<<<(BB * SS) / 8, 256>>>(key);
    sgm_kernel<<<BB, 256>>>(memory, value, out);
}

// round 14
// speedup vs baseline: 1.1673x; 1.0318x over previous
#include <cuda_runtime.h>
#include <math.h>

#define BB 64
#define SS 1024
#define DK 128
#define DV 128
#define HALF 64
#define KST 68   // padded half-stride (floats); halves at +0 / +68

// Normalized keys (32 MB) + adjacent-key dots c[s] (for fallback) + spec flag.
__device__ float g_kn[(size_t)BB * SS * DK];
__device__ float g_c[BB * SS];
__device__ int   g_flag;

// ---------------------------------------------------------------------------
// Pre-pass: normalize keys, adjacent normalized dots, clear flag.
// ---------------------------------------------------------------------------
__global__ void prep_kernel(const float* __restrict__ key) {
    if (blockIdx.x == 0 && threadIdx.x == 0) g_flag = 0;
    int row = blockIdx.x * 8 + (threadIdx.x >> 5);
    int lane = threadIdx.x & 31;
    if (row >= BB * SS) return;
    int s = row & (SS - 1);

    float4 kv = reinterpret_cast<const float4*>(key)[(size_t)row * 32 + lane];
    float nn = kv.x * kv.x + kv.y * kv.y + kv.z * kv.z + kv.w * kv.w;
    float np = 0.f, dd = 0.f;
    if (s > 0) {
        float4 kp = reinterpret_cast<const float4*>(key)[(size_t)(row - 1) * 32 + lane];
        np = kp.x * kp.x + kp.y * kp.y + kp.z * kp.z + kp.w * kp.w;
        dd = kv.x * kp.x + kv.y * kp.y + kv.z * kp.z + kv.w * kp.w;
    }
    #pragma unroll
    for (int o = 16; o; o >>= 1) {
        nn += __shfl_xor_sync(0xffffffffu, nn, o);
        np += __shfl_xor_sync(0xffffffffu, np, o);
        dd += __shfl_xor_sync(0xffffffffu, dd, o);
    }
    float invn = 1.0f / (sqrtf(nn) + 1e-6f);
    float4 o4 = make_float4(kv.x * invn, kv.y * invn, kv.z * invn, kv.w * invn);
    reinterpret_cast<float4*>(g_kn)[(size_t)row * 32 + lane] = o4;
    if (lane == 0)
        g_c[row] = (s > 0) ? dd * invn * (1.0f / (sqrtf(np) + 1e-6f)) : 0.0f;
}

// ---------------------------------------------------------------------------
// Packed f32x2 helpers
// ---------------------------------------------------------------------------
__device__ __forceinline__ unsigned long long pack2(float x) {
    unsigned long long r;
    asm("mov.b64 %0, {%1, %1};" : "=l"(r) : "f"(x));
    return r;
}
__device__ __forceinline__ void fma2(unsigned long long& d,
                                     unsigned long long a, unsigned long long b) {
    asm("fma.rn.f32x2 %0, %1, %2, %0;" : "+l"(d) : "l"(a), "l"(b));
}
__device__ __forceinline__ float sum2(unsigned long long a) {
    float lo, hi;
    asm("mov.b64 {%0, %1}, %2;" : "=f"(lo), "=f"(hi) : "l"(a));
    return lo + hi;
}

// ---------------------------------------------------------------------------
// FAST PATH: assumes every gate saturates to exactly 1.0f. Then the update
// coefficient u_r = pred_r + 0.1*sur_r is per-row local: no block coupling on
// the memory recurrence. The gate (output) is computed via a lagged reduce
// and VERIFIED == 1.0f; any deviation sets g_flag for the exact fallback.
// ---------------------------------------------------------------------------
__global__ __launch_bounds__(256, 1) void sgm_fast(
    const float* __restrict__ memory,
    const float* __restrict__ value,
    float* __restrict__ out)
{
    const int b = blockIdx.x, t = threadIdx.x;
    const int r = t >> 1, h = t & 1;
    const int lane = t & 31, wid = t >> 5;

    __shared__ __align__(16) float sk[2][2 * KST];
    __shared__ float red[2][8];

    const float* knb = g_kn + (size_t)b * SS * DK;
    const float* vb  = value + (size_t)b * SS * DV;
    float* gates = out + (size_t)BB * DV * DK + (size_t)b * SS;

    unsigned long long m2[HALF / 2];
    {
        const ulonglong2* mb = reinterpret_cast<const ulonglong2*>(
            memory + (size_t)b * DV * DK + (size_t)r * DK + h * HALF);
        #pragma unroll
        for (int j = 0; j < HALF / 4; ++j) {
            ulonglong2 x = mb[j];
            m2[2 * j] = x.x; m2[2 * j + 1] = x.y;
        }
    }

    if (t < DK) sk[0][(t >> 6) * KST + (t & 63)] = knb[t];
    float vs = vb[r];
    __syncthreads();

    int bad = 0;

    for (int s = 0; s < SS; ++s) {
        const int sn = (s + 1 < SS) ? s + 1 : s;
        float knxt = (t < DK) ? knb[(size_t)sn * DK + t] : 0.0f;
        float vnxt = vb[(size_t)sn * DV + r];

        // A: pred = m_row . kn[s]
        const ulonglong2* kc = reinterpret_cast<const ulonglong2*>(&sk[s & 1][h * KST]);
        unsigned long long a0 = 0, a1 = 0, a2 = 0, a3 = 0;
        #pragma unroll
        for (int j = 0; j < 4; ++j) {
            ulonglong2 k0 = kc[4 * j], k1 = kc[4 * j + 1];
            ulonglong2 k2 = kc[4 * j + 2], k3 = kc[4 * j + 3];
            fma2(a0, m2[8 * j + 0], k0.x); fma2(a1, m2[8 * j + 1], k0.y);
            fma2(a2, m2[8 * j + 2], k1.x); fma2(a3, m2[8 * j + 3], k1.y);
            fma2(a0, m2[8 * j + 4], k2.x); fma2(a1, m2[8 * j + 5], k2.y);
            fma2(a2, m2[8 * j + 6], k3.x); fma2(a3, m2[8 * j + 7], k3.y);
        }
        float part = (sum2(a0) + sum2(a1)) + (sum2(a2) + sum2(a3));
        float pred = part + __shfl_xor_sync(0xffffffffu, part, 1);
        float sur = pred - vs;
        float w = fmaf(0.1f, sur, pred);     // u (gate assumed exactly 1.0f)

        // B: immediate rank-1 update m -= w * kn[s] (u is local; no coupling)
        unsigned long long nu = pack2(-w);
        #pragma unroll
        for (int j = 0; j < 4; ++j) {
            ulonglong2 k0 = kc[4 * j], k1 = kc[4 * j + 1];
            ulonglong2 k2 = kc[4 * j + 2], k3 = kc[4 * j + 3];
            fma2(m2[8 * j + 0], k0.x, nu); fma2(m2[8 * j + 1], k0.y, nu);
            fma2(m2[8 * j + 2], k1.x, nu); fma2(m2[8 * j + 3], k1.y, nu);
            fma2(m2[8 * j + 4], k2.x, nu); fma2(m2[8 * j + 5], k2.y, nu);
            fma2(m2[8 * j + 6], k3.x, nu); fma2(m2[8 * j + 7], k3.y, nu);
        }

        // C: lagged reduce for the gate OUTPUT (off the memory chain)
        float ss2 = 0.5f * sur * sur;
        #pragma unroll
        for (int o = 16; o; o >>= 1) ss2 += __shfl_xor_sync(0xffffffffu, ss2, o);
        if (lane == 0) red[s & 1][wid] = ss2;

        // D: finalize gate of step s-1; verify saturation
        if (s > 0) {
            const float* rp = red[(s - 1) & 1];
            float tot = ((rp[0] + rp[1]) + (rp[2] + rp[3]))
                      + ((rp[4] + rp[5]) + (rp[6] + rp[7]));
            float snorm = sqrtf(tot);
            float gate = 1.0f / (1.0f + __expf((0.1f - snorm) * 10.0f));
            if (t == 0) gates[s - 1] = gate;
            bad |= (gate != 1.0f);
        }

        vs = vnxt;
        if (t < DK) sk[(s + 1) & 1][(t >> 6) * KST + (t & 63)] = knxt;
        __syncthreads();
    }

    // epilogue: gate for step SS-1
    {
        const float* rp = red[(SS - 1) & 1];
        float tot = ((rp[0] + rp[1]) + (rp[2] + rp[3]))
                  + ((rp[4] + rp[5]) + (rp[6] + rp[7]));
        float snorm = sqrtf(tot);
        float gate = 1.0f / (1.0f + __expf((0.1f - snorm) * 10.0f));
        if (t == 0) gates[SS - 1] = gate;
        bad |= (gate != 1.0f);
    }
    if (bad) g_flag = 1;

    {
        ulonglong2* ob = reinterpret_cast<ulonglong2*>(
            out + (size_t)b * DV * DK + (size_t)r * DK + h * HALF);
        #pragma unroll
        for (int j = 0; j < HALF / 4; ++j) {
            ulonglong2 x;
            x.x = m2[2 * j]; x.y = m2[2 * j + 1];
            ob[j] = x;
        }
    }
}

// ---------------------------------------------------------------------------
// FALLBACK: verbatim R4 kernel (verified 600us / rel_err 3.8e-7); runs only
// if the saturation assumption failed (g_flag set by sgm_fast).
// ---------------------------------------------------------------------------
__global__ __launch_bounds__(256, 1) void sgm_fallback(
    const float* __restrict__ memory,
    const float* __restrict__ value,
    float* __restrict__ out)
{
    if (*((volatile int*)&g_flag) == 0) return;

    const int b = blockIdx.x;
    const int t = threadIdx.x;
    const int r = t >> 1;
    const int h = t & 1;
    const int lane = t & 31;
    const int wid = t >> 5;

    __shared__ __align__(16) float sk[3][2 * KST];
    __shared__ float red[2][8];

    const float* knb = g_kn + (size_t)b * SS * DK;
    const float* vb  = value + (size_t)b * SS * DV;
    const float* cb  = g_c + (size_t)b * SS;
    float* gates = out + (size_t)BB * DV * DK + (size_t)b * SS;

    unsigned long long m2[HALF / 2];
    {
        const ulonglong2* mb = reinterpret_cast<const ulonglong2*>(
            memory + (size_t)b * DV * DK + (size_t)r * DK + h * HALF);
        #pragma unroll
        for (int j = 0; j < HALF / 4; ++j) {
            ulonglong2 x = mb[j];
            m2[2 * j] = x.x; m2[2 * j + 1] = x.y;
        }
    }

    if (t < DK) sk[0][(t >> 6) * KST + (t & 63)] = knb[t];
    float vs = vb[r];
    float ccur = cb[1];
    __syncthreads();

    float pprev, sprev;
    {
        const ulonglong2* kc = reinterpret_cast<const ulonglong2*>(&sk[0][h * KST]);
        unsigned long long a0 = 0, a1 = 0, a2 = 0, a3 = 0;
        #pragma unroll
        for (int j = 0; j < 4; ++j) {
            ulonglong2 k0 = kc[4 * j], k1 = kc[4 * j + 1];
            ulonglong2 k2 = kc[4 * j + 2], k3 = kc[4 * j + 3];
            fma2(a0, m2[8 * j + 0], k0.x); fma2(a1, m2[8 * j + 1], k0.y);
            fma2(a2, m2[8 * j + 2], k1.x); fma2(a3, m2[8 * j + 3], k1.y);
            fma2(a0, m2[8 * j + 4], k2.x); fma2(a1, m2[8 * j + 5], k2.y);
            fma2(a2, m2[8 * j + 6], k3.x); fma2(a3, m2[8 * j + 7], k3.y);
        }
        float part = (sum2(a0) + sum2(a1)) + (sum2(a2) + sum2(a3));
        float pred = part + __shfl_xor_sync(0xffffffffu, part, 1);
        float sur = pred - vs;
        float ss2 = 0.5f * sur * sur;
        #pragma unroll
        for (int o = 16; o; o >>= 1) ss2 += __shfl_xor_sync(0xffffffffu, ss2, o);
        if (lane == 0) red[0][wid] = ss2;
        pprev = pred; sprev = sur;
    }
    if (t < DK) sk[1][(t >> 6) * KST + (t & 63)] = knb[DK + t];
    vs = vb[DV + r];
    __syncthreads();

    int ip = 2, ic = 0, inx = 1;

    for (int s = 1; s < SS; ++s) {
        { int tmp = ip; ip = ic; ic = inx; inx = tmp; }

        const int sn = (s + 1 < SS) ? s + 1 : s;
        float knxt = (t < DK) ? knb[(size_t)sn * DK + t] : 0.0f;
        float vnxt = vb[(size_t)sn * DV + r];
        float cnxt = cb[sn];

        const ulonglong2* kc = reinterpret_cast<const ulonglong2*>(&sk[ic][h * KST]);
        unsigned long long a0 = 0, a1 = 0, a2 = 0, a3 = 0;
        #pragma unroll
        for (int j = 0; j < 4; ++j) {
            ulonglong2 k0 = kc[4 * j], k1 = kc[4 * j + 1];
            ulonglong2 k2 = kc[4 * j + 2], k3 = kc[4 * j + 3];
            fma2(a0, m2[8 * j + 0], k0.x); fma2(a1, m2[8 * j + 1], k0.y);
            fma2(a2, m2[8 * j + 2], k1.x); fma2(a3, m2[8 * j + 3], k1.y);
            fma2(a0, m2[8 * j + 4], k2.x); fma2(a1, m2[8 * j + 5], k2.y);
            fma2(a2, m2[8 * j + 6], k3.x); fma2(a3, m2[8 * j + 7], k3.y);
        }

        const float* rp = red[(s - 1) & 1];
        float tot = ((rp[0] + rp[1]) + (rp[2] + rp[3]))
                  + ((rp[4] + rp[5]) + (rp[6] + rp[7]));
        float snorm = sqrtf(tot);
        float gate = 1.0f / (1.0f + __expf((0.1f - snorm) * 10.0f));
        if (t == 0) gates[s - 1] = gate;
        float u = gate * fmaf(0.1f, sprev, pprev);

        unsigned long long nu = pack2(-u);
        const ulonglong2* kp = reinterpret_cast<const ulonglong2*>(&sk[ip][h * KST]);
        #pragma unroll
        for (int j = 0; j < 4; ++j) {
            ulonglong2 k0 = kp[4 * j], k1 = kp[4 * j + 1];
            ulonglong2 k2 = kp[4 * j + 2], k3 = kp[4 * j + 3];
            fma2(m2[8 * j + 0], k0.x, nu); fma2(m2[8 * j + 1], k0.y, nu);
            fma2(m2[8 * j + 2], k1.x, nu); fma2(m2[8 * j + 3], k1.y, nu);
            fma2(m2[8 * j + 4], k2.x, nu); fma2(m2[8 * j + 5], k2.y, nu);
            fma2(m2[8 * j + 6], k3.x, nu); fma2(m2[8 * j + 7], k3.y, nu);
        }

        float part = (sum2(a0) + sum2(a1)) + (sum2(a2) + sum2(a3));
        float pred = (part + __shfl_xor_sync(0xffffffffu, part, 1)) - u * ccur;
        float sur = pred - vs;
        float ss2 = 0.5f * sur * sur;
        #pragma unroll
        for (int o = 16; o; o >>= 1) ss2 += __shfl_xor_sync(0xffffffffu, ss2, o);
        if (lane == 0) red[s & 1][wid] = ss2;

        pprev = pred; sprev = sur; vs = vnxt; ccur = cnxt;
        if (t < DK) sk[inx][(t >> 6) * KST + (t & 63)] = knxt;
        __syncthreads();
    }

    {
        const float* rp = red[(SS - 1) & 1];
        float tot = ((rp[0] + rp[1]) + (rp[2] + rp[3]))
                  + ((rp[4] + rp[5]) + (rp[6] + rp[7]));
        float snorm = sqrtf(tot);
        float gate = 1.0f / (1.0f + __expf((0.1f - snorm) * 10.0f));
        if (t == 0) gates[SS - 1] = gate;
        float u = gate * fmaf(0.1f, sprev, pprev);
        unsigned long long nu = pack2(-u);
        const ulonglong2* kp = reinterpret_cast<const ulonglong2*>(&sk[ic][h * KST]);
        #pragma unroll
        for (int j = 0; j < 4; ++j) {
            ulonglong2 k0 = kp[4 * j], k1 = kp[4 * j + 1];
            ulonglong2 k2 = kp[4 * j + 2], k3 = kp[4 * j + 3];
            fma2(m2[8 * j + 0], k0.x, nu); fma2(m2[8 * j + 1], k0.y, nu);
            fma2(m2[8 * j + 2], k1.x, nu); fma2(m2[8 * j + 3], k1.y, nu);
            fma2(m2[8 * j + 4], k2.x, nu); fma2(m2[8 * j + 5], k2.y, nu);
            fma2(m2[8 * j + 6], k3.x, nu); fma2(m2[8 * j + 7], k3.y, nu);
        }
    }

    {
        ulonglong2* ob = reinterpret_cast<ulonglong2*>(
            out + (size_t)b * DV * DK + (size_t)r * DK + h * HALF);
        #pragma unroll
        for (int j = 0; j < HALF / 4; ++j) {
            ulonglong2 x;
            x.x = m2[2 * j]; x.y = m2[2 * j + 1];
            ob[j] = x;
        }
    }
}

extern "C" void kernel_launch(void* const* d_in, const int* in_sizes, int n_in,
                              void* d_out, int out_size) {
    const float* memory = (const float*)d_in[0];
    const float* key    = (const float*)d_in[1];
    const float* value  = (const float*)d_in[2];
    float* out = (float*)d_out;

    prep_kernel<<<(BB * SS) / 8, 256>>>(key);
    sgm_fast<<<BB, 256>>>(memory, value, out);
    sgm_fallback<<<BB, 256>>>(memory, value, out);
}

// round 15
// speedup vs baseline: 2.0865x; 1.7874x over previous
#include <cuda_runtime.h>
#include <math.h>

#define BB 64
#define SS 1024
#define DK 128
#define DV 128
#define HALF 64
#define KST 68      // padded half-stride (floats); halves at +0 / +68
#define CHUNK 32
#define NCHK (SS / CHUNK)

// Normalized keys (32 MB), adjacent dots (fallback), per-step warp partials,
// speculation flag.
__device__ float g_kn[(size_t)BB * SS * DK];
__device__ float g_c[BB * SS];
__device__ float g_red[(size_t)BB * SS * 8];
__device__ int   g_flag;

// ---------------------------------------------------------------------------
// Pre-pass: normalize keys, adjacent normalized dots, clear flag.
// ---------------------------------------------------------------------------
__global__ void prep_kernel(const float* __restrict__ key) {
    if (blockIdx.x == 0 && threadIdx.x == 0) g_flag = 0;
    int row = blockIdx.x * 8 + (threadIdx.x >> 5);
    int lane = threadIdx.x & 31;
    if (row >= BB * SS) return;
    int s = row & (SS - 1);

    float4 kv = reinterpret_cast<const float4*>(key)[(size_t)row * 32 + lane];
    float nn = kv.x * kv.x + kv.y * kv.y + kv.z * kv.z + kv.w * kv.w;
    float np = 0.f, dd = 0.f;
    if (s > 0) {
        float4 kp = reinterpret_cast<const float4*>(key)[(size_t)(row - 1) * 32 + lane];
        np = kp.x * kp.x + kp.y * kp.y + kp.z * kp.z + kp.w * kp.w;
        dd = kv.x * kp.x + kv.y * kp.y + kv.z * kp.z + kv.w * kp.w;
    }
    #pragma unroll
    for (int o = 16; o; o >>= 1) {
        nn += __shfl_xor_sync(0xffffffffu, nn, o);
        np += __shfl_xor_sync(0xffffffffu, np, o);
        dd += __shfl_xor_sync(0xffffffffu, dd, o);
    }
    float invn = 1.0f / (sqrtf(nn) + 1e-6f);
    float4 o4 = make_float4(kv.x * invn, kv.y * invn, kv.z * invn, kv.w * invn);
    reinterpret_cast<float4*>(g_kn)[(size_t)row * 32 + lane] = o4;
    if (lane == 0)
        g_c[row] = (s > 0) ? dd * invn * (1.0f / (sqrtf(np) + 1e-6f)) : 0.0f;
}

// ---------------------------------------------------------------------------
// Packed f32x2 + cp.async helpers
// ---------------------------------------------------------------------------
__device__ __forceinline__ unsigned long long pack2(float x) {
    unsigned long long r;
    asm("mov.b64 %0, {%1, %1};" : "=l"(r) : "f"(x));
    return r;
}
__device__ __forceinline__ void fma2(unsigned long long& d,
                                     unsigned long long a, unsigned long long b) {
    asm("fma.rn.f32x2 %0, %1, %2, %0;" : "+l"(d) : "l"(a), "l"(b));
}
__device__ __forceinline__ float sum2(unsigned long long a) {
    float lo, hi;
    asm("mov.b64 {%0, %1}, %2;" : "=f"(lo), "=f"(hi) : "l"(a));
    return lo + hi;
}
__device__ __forceinline__ unsigned smem_u32(const void* p) {
    unsigned r;
    asm("{ .reg .u64 t; cvta.to.shared.u64 t, %1; cvt.u32.u64 %0, t; }"
        : "=r"(r) : "l"(p));
    return r;
}
#define CP_ASYNC16(sa, gp) \
    asm volatile("cp.async.cg.shared.global [%0], [%1], 16;" :: "r"(sa), "l"(gp) : "memory")
#define CP_COMMIT() asm volatile("cp.async.commit_group;" ::: "memory")
#define CP_WAIT0()  asm volatile("cp.async.wait_group 0;" ::: "memory")

// ---------------------------------------------------------------------------
// FAST PATH (barrier-free scan): gate assumed saturated to exactly 1.0f, so
// u_r = pred_r + 0.1*sur_r is per-row local and the recurrence is WARP-LOCAL.
// k staged in 32-step double-buffered chunks (one barrier per chunk = 32
// total). Per-step warp partials of ||sur||^2 go to global scratch; a final
// epilogue computes/verifies all gates and sets g_flag on any non-saturation.
// ---------------------------------------------------------------------------
__global__ __launch_bounds__(256, 1) void sgm_fast(
    const float* __restrict__ memory,
    const float* __restrict__ value,
    float* __restrict__ out)
{
    const int b = blockIdx.x, t = threadIdx.x;
    const int r = t >> 1, h = t & 1;
    const int lane = t & 31, wid = t >> 5;

    __shared__ __align__(16) float skc[2][CHUNK][2 * KST];

    const float* knb = g_kn + (size_t)b * SS * DK;
    const float* vb  = value + (size_t)b * SS * DV;
    float* redb = g_red + (size_t)b * SS * 8;
    float* gates = out + (size_t)BB * DV * DK + (size_t)b * SS;

    // Load my 64-float half of memory row r as 32 packed f32x2.
    unsigned long long m2[HALF / 2];
    {
        const ulonglong2* mb = reinterpret_cast<const ulonglong2*>(
            memory + (size_t)b * DV * DK + (size_t)r * DK + h * HALF);
        #pragma unroll
        for (int j = 0; j < HALF / 4; ++j) {
            ulonglong2 x = mb[j];
            m2[2 * j] = x.x; m2[2 * j + 1] = x.y;
        }
    }

    // Stage chunk 0.
    {
        #pragma unroll
        for (int q = 0; q < 4; ++q) {
            int idx = t * 4 + q;                 // 0..1023
            int row = idx >> 5;                  // 0..31
            int col = (idx & 31) * 4;            // 0..124
            CP_ASYNC16(smem_u32(&skc[0][row][(col >> 6) * KST + (col & 63)]),
                       knb + (size_t)row * DK + col);
        }
        CP_COMMIT();
    }
    float vs = vb[r];
    float v1 = vb[DV + r];
    CP_WAIT0();
    __syncthreads();

    for (int c = 0; c < NCHK; ++c) {
        // Stage chunk c+1 into the other buffer (read during chunk c-1;
        // the barrier at the end of chunk c-1 made it free).
        if (c + 1 < NCHK) {
            const float* src = knb + (size_t)(c + 1) * CHUNK * DK;
            #pragma unroll
            for (int q = 0; q < 4; ++q) {
                int idx = t * 4 + q;
                int row = idx >> 5;
                int col = (idx & 31) * 4;
                CP_ASYNC16(smem_u32(&skc[(c + 1) & 1][row][(col >> 6) * KST + (col & 63)]),
                           src + (size_t)row * DK + col);
            }
        }
        CP_COMMIT();

        // Barrier-free scan over this chunk's 32 steps (warp-local recurrence).
        for (int j = 0; j < CHUNK; ++j) {
            const int s = c * CHUNK + j;
            float v2 = (s + 2 < SS) ? vb[(size_t)(s + 2) * DV + r] : 0.0f;

            // load k half into regs (shared -> reg once; reused by update)
            const ulonglong2* kc = reinterpret_cast<const ulonglong2*>(
                &skc[c & 1][j][h * KST]);
            unsigned long long kk[32];
            unsigned long long a0 = 0, a1 = 0, a2 = 0, a3 = 0;
            #pragma unroll
            for (int q = 0; q < 4; ++q) {
                ulonglong2 k0 = kc[4 * q], k1 = kc[4 * q + 1];
                ulonglong2 k2 = kc[4 * q + 2], k3 = kc[4 * q + 3];
                kk[8 * q + 0] = k0.x; kk[8 * q + 1] = k0.y;
                kk[8 * q + 2] = k1.x; kk[8 * q + 3] = k1.y;
                kk[8 * q + 4] = k2.x; kk[8 * q + 5] = k2.y;
                kk[8 * q + 6] = k3.x; kk[8 * q + 7] = k3.y;
                fma2(a0, m2[8 * q + 0], k0.x); fma2(a1, m2[8 * q + 1], k0.y);
                fma2(a2, m2[8 * q + 2], k1.x); fma2(a3, m2[8 * q + 3], k1.y);
                fma2(a0, m2[8 * q + 4], k2.x); fma2(a1, m2[8 * q + 5], k2.y);
                fma2(a2, m2[8 * q + 6], k3.x); fma2(a3, m2[8 * q + 7], k3.y);
            }
            float part = (sum2(a0) + sum2(a1)) + (sum2(a2) + sum2(a3));
            float pred = part + __shfl_xor_sync(0xffffffffu, part, 1);
            float sur = pred - vs;
            float w = fmaf(0.1f, sur, pred);     // u with gate == 1.0f

            // immediate per-row rank-1 update (warp-local, no coupling)
            unsigned long long nu = pack2(-w);
            #pragma unroll
            for (int q = 0; q < 8; ++q) {
                fma2(m2[4 * q + 0], kk[4 * q + 0], nu);
                fma2(m2[4 * q + 1], kk[4 * q + 1], nu);
                fma2(m2[4 * q + 2], kk[4 * q + 2], nu);
                fma2(m2[4 * q + 3], kk[4 * q + 3], nu);
            }

            // warp partial of ||sur||^2 -> global scratch (off critical path)
            float ss2 = 0.5f * sur * sur;
            #pragma unroll
            for (int o = 16; o; o >>= 1)
                ss2 += __shfl_xor_sync(0xffffffffu, ss2, o);
            if (lane == 0) redb[(size_t)s * 8 + wid] = ss2;

            vs = v1; v1 = v2;
        }

        CP_WAIT0();
        __syncthreads();   // chunk boundary: staging visible, old buffer free
    }

    // Store final memory half.
    {
        ulonglong2* ob = reinterpret_cast<ulonglong2*>(
            out + (size_t)b * DV * DK + (size_t)r * DK + h * HALF);
        #pragma unroll
        for (int j = 0; j < HALF / 4; ++j) {
            ulonglong2 x;
            x.x = m2[2 * j]; x.y = m2[2 * j + 1];
            ob[j] = x;
        }
    }

    // Epilogue: compute + verify all gates (partials visible: the loop's
    // final __syncthreads fences this block's global writes).
    int bad = 0;
    #pragma unroll
    for (int q = 0; q < SS / 256; ++q) {
        int s = t + q * 256;
        const float4* rp = reinterpret_cast<const float4*>(&redb[(size_t)s * 8]);
        float4 rA = rp[0], rB = rp[1];
        float tot = ((rA.x + rA.y) + (rA.z + rA.w))
                  + ((rB.x + rB.y) + (rB.z + rB.w));
        float snorm = sqrtf(tot);
        float gate = 1.0f / (1.0f + __expf((0.1f - snorm) * 10.0f));
        gates[s] = gate;
        bad |= (gate != 1.0f);
    }
    if (bad) g_flag = 1;
}

// ---------------------------------------------------------------------------
// FALLBACK: verbatim R4 kernel (verified 600us / rel_err 3.8e-7); runs only
// if the saturation assumption failed.
// ---------------------------------------------------------------------------
__global__ __launch_bounds__(256, 1) void sgm_fallback(
    const float* __restrict__ memory,
    const float* __restrict__ value,
    float* __restrict__ out)
{
    if (*((volatile int*)&g_flag) == 0) return;

    const int b = blockIdx.x;
    const int t = threadIdx.x;
    const int r = t >> 1;
    const int h = t & 1;
    const int lane = t & 31;
    const int wid = t >> 5;

    __shared__ __align__(16) float sk[3][2 * KST];
    __shared__ float red[2][8];

    const float* knb = g_kn + (size_t)b * SS * DK;
    const float* vb  = value + (size_t)b * SS * DV;
    const float* cb  = g_c + (size_t)b * SS;
    float* gates = out + (size_t)BB * DV * DK + (size_t)b * SS;

    unsigned long long m2[HALF / 2];
    {
        const ulonglong2* mb = reinterpret_cast<const ulonglong2*>(
            memory + (size_t)b * DV * DK + (size_t)r * DK + h * HALF);
        #pragma unroll
        for (int j = 0; j < HALF / 4; ++j) {
            ulonglong2 x = mb[j];
            m2[2 * j] = x.x; m2[2 * j + 1] = x.y;
        }
    }

    if (t < DK) sk[0][(t >> 6) * KST + (t & 63)] = knb[t];
    float vs = vb[r];
    float ccur = cb[1];
    __syncthreads();

    float pprev, sprev;
    {
        const ulonglong2* kc = reinterpret_cast<const ulonglong2*>(&sk[0][h * KST]);
        unsigned long long a0 = 0, a1 = 0, a2 = 0, a3 = 0;
        #pragma unroll
        for (int j = 0; j < 4; ++j) {
            ulonglong2 k0 = kc[4 * j], k1 = kc[4 * j + 1];
            ulonglong2 k2 = kc[4 * j + 2], k3 = kc[4 * j + 3];
            fma2(a0, m2[8 * j + 0], k0.x); fma2(a1, m2[8 * j + 1], k0.y);
            fma2(a2, m2[8 * j + 2], k1.x); fma2(a3, m2[8 * j + 3], k1.y);
            fma2(a0, m2[8 * j + 4], k2.x); fma2(a1, m2[8 * j + 5], k2.y);
            fma2(a2, m2[8 * j + 6], k3.x); fma2(a3, m2[8 * j + 7], k3.y);
        }
        float part = (sum2(a0) + sum2(a1)) + (sum2(a2) + sum2(a3));
        float pred = part + __shfl_xor_sync(0xffffffffu, part, 1);
        float sur = pred - vs;
        float ss2 = 0.5f * sur * sur;
        #pragma unroll
        for (int o = 16; o; o >>= 1) ss2 += __shfl_xor_sync(0xffffffffu, ss2, o);
        if (lane == 0) red[0][wid] = ss2;
        pprev = pred; sprev = sur;
    }
    if (t < DK) sk[1][(t >> 6) * KST + (t & 63)] = knb[DK + t];
    vs = vb[DV + r];
    __syncthreads();

    int ip = 2, ic = 0, inx = 1;

    for (int s = 1; s < SS; ++s) {
        { int tmp = ip; ip = ic; ic = inx; inx = tmp; }

        const int sn = (s + 1 < SS) ? s + 1 : s;
        float knxt = (t < DK) ? knb[(size_t)sn * DK + t] : 0.0f;
        float vnxt = vb[(size_t)sn * DV + r];
        float cnxt = cb[sn];

        const ulonglong2* kc = reinterpret_cast<const ulonglong2*>(&sk[ic][h * KST]);
        unsigned long long a0 = 0, a1 = 0, a2 = 0, a3 = 0;
        #pragma unroll
        for (int j = 0; j < 4; ++j) {
            ulonglong2 k0 = kc[4 * j], k1 = kc[4 * j + 1];
            ulonglong2 k2 = kc[4 * j + 2], k3 = kc[4 * j + 3];
            fma2(a0, m2[8 * j + 0], k0.x); fma2(a1, m2[8 * j + 1], k0.y);
            fma2(a2, m2[8 * j + 2], k1.x); fma2(a3, m2[8 * j + 3], k1.y);
            fma2(a0, m2[8 * j + 4], k2.x); fma2(a1, m2[8 * j + 5], k2.y);
            fma2(a2, m2[8 * j + 6], k3.x); fma2(a3, m2[8 * j + 7], k3.y);
        }

        const float* rp = red[(s - 1) & 1];
        float tot = ((rp[0] + rp[1]) + (rp[2] + rp[3]))
                  + ((rp[4] + rp[5]) + (rp[6] + rp[7]));
        float snorm = sqrtf(tot);
        float gate = 1.0f / (1.0f + __expf((0.1f - snorm) * 10.0f));
        if (t == 0) gates[s - 1] = gate;
        float u = gate * fmaf(0.1f, sprev, pprev);

        unsigned long long nu = pack2(-u);
        const ulonglong2* kp = reinterpret_cast<const ulonglong2*>(&sk[ip][h * KST]);
        #pragma unroll
        for (int j = 0; j < 4; ++j) {
            ulonglong2 k0 = kp[4 * j], k1 = kp[4 * j + 1];
            ulonglong2 k2 = kp[4 * j + 2], k3 = kp[4 * j + 3];
            fma2(m2[8 * j + 0], k0.x, nu); fma2(m2[8 * j + 1], k0.y, nu);
            fma2(m2[8 * j + 2], k1.x, nu); fma2(m2[8 * j + 3], k1.y, nu);
            fma2(m2[8 * j + 4], k2.x, nu); fma2(m2[8 * j + 5], k2.y, nu);
            fma2(m2[8 * j + 6], k3.x, nu); fma2(m2[8 * j + 7], k3.y, nu);
        }

        float part = (sum2(a0) + sum2(a1)) + (sum2(a2) + sum2(a3));
        float pred = (part + __shfl_xor_sync(0xffffffffu, part, 1)) - u * ccur;
        float sur = pred - vs;
        float ss2 = 0.5f * sur * sur;
        #pragma unroll
        for (int o = 16; o; o >>= 1) ss2 += __shfl_xor_sync(0xffffffffu, ss2, o);
        if (lane == 0) red[s & 1][wid] = ss2;

        pprev = pred; sprev = sur; vs = vnxt; ccur = cnxt;
        if (t < DK) sk[inx][(t >> 6) * KST + (t & 63)] = knxt;
        __syncthreads();
    }

    {
        const float* rp = red[(SS - 1) & 1];
        float tot = ((rp[0] + rp[1]) + (rp[2] + rp[3]))
                  + ((rp[4] + rp[5]) + (rp[6] + rp[7]));
        float snorm = sqrtf(tot);
        float gate = 1.0f / (1.0f + __expf((0.1f - snorm) * 10.0f));
        if (t == 0) gates[SS - 1] = gate;
        float u = gate * fmaf(0.1f, sprev, pprev);
        unsigned long long nu = pack2(-u);
        const ulonglong2* kp = reinterpret_cast<const ulonglong2*>(&sk[ic][h * KST]);
        #pragma unroll
        for (int j = 0; j < 4; ++j) {
            ulonglong2 k0 = kp[4 * j], k1 = kp[4 * j + 1];
            ulonglong2 k2 = kp[4 * j + 2], k3 = kp[4 * j + 3];
            fma2(m2[8 * j + 0], k0.x, nu); fma2(m2[8 * j + 1], k0.y, nu);
            fma2(m2[8 * j + 2], k1.x, nu); fma2(m2[8 * j + 3], k1.y, nu);
            fma2(m2[8 * j + 4], k2.x, nu); fma2(m2[8 * j + 5], k2.y, nu);
            fma2(m2[8 * j + 6], k3.x, nu); fma2(m2[8 * j + 7], k3.y, nu);
        }
    }

    {
        ulonglong2* ob = reinterpret_cast<ulonglong2*>(
            out + (size_t)b * DV * DK + (size_t)r * DK + h * HALF);
        #pragma unroll
        for (int j = 0; j < HALF / 4; ++j) {
            ulonglong2 x;
            x.x = m2[2 * j]; x.y = m2[2 * j + 1];
            ob[j] = x;
        }
    }
}

extern "C" void kernel_launch(void* const* d_in, const int* in_sizes, int n_in,
                              void* d_out, int out_size) {
    const float* memory = (const float*)d_in[0];
    const float* key    = (const float*)d_in[1];
    const float* value  = (const float*)d_in[2];
    float* out = (float*)d_out;

    prep_kernel<<<(BB * SS) / 8, 256>>>(key);
    sgm_fast<<<BB, 256>>>(memory, value, out);
    sgm_fallback<<<BB, 256>>>(memory, value, out);
}